// round 1
// baseline (speedup 1.0000x reference)
#include <cuda_runtime.h>
#include <math.h>

#define D_MODEL 2048
#define S_LEN   2048
#define BATCH   2
#define NHEADS  16
#define NKV     4
#define NGRP    4
#define HD      128
#define KVD     (NKV*HD)        /* 512  */
#define MROWS   (BATCH*S_LEN)   /* 4096 */

// -------- scratch (device globals; no allocation allowed) --------
__device__ float g_Q  [(size_t)MROWS * D_MODEL];                    // 32 MB
__device__ float g_K  [(size_t)MROWS * KVD];                        // 8 MB
__device__ float g_V  [(size_t)MROWS * KVD];                        // 8 MB
__device__ float g_ctx[(size_t)MROWS * D_MODEL];                    // 32 MB
__device__ float g_attn[(size_t)BATCH * NHEADS * S_LEN * S_LEN];    // 512 MB

// ============================================================================
// Generic C = X * W^T * scale + bias   (X:[M,Kd] lda, W:[N,Kd] ldb, C:[M,N] ldc)
// BM=BN=64, BK=16, 256 threads, 4x4 per thread, fp32.
// ============================================================================
__global__ __launch_bounds__(256) void gemm_xwt(
    const float* __restrict__ X, const float* __restrict__ W,
    const float* __restrict__ bias, float* __restrict__ C,
    int M, int N, int Kd, int lda, int ldb, int ldc)
{
    const int m0 = blockIdx.y * 64;
    const int n0 = blockIdx.x * 64;
    __shared__ float As[16][64];
    __shared__ float Bs[16][64];
    const int t  = threadIdx.x;
    const int lr = t >> 2;          // 0..63
    const int lc = (t & 3) * 4;     // 0,4,8,12
    const int ty = t >> 4;          // 0..15
    const int tx = t & 15;          // 0..15
    float acc[4][4] = {};

    for (int k0 = 0; k0 < Kd; k0 += 16) {
        float4 xa = *(const float4*)(X + (size_t)(m0 + lr) * lda + k0 + lc);
        float4 wb = *(const float4*)(W + (size_t)(n0 + lr) * ldb + k0 + lc);
        As[lc+0][lr] = xa.x; As[lc+1][lr] = xa.y; As[lc+2][lr] = xa.z; As[lc+3][lr] = xa.w;
        Bs[lc+0][lr] = wb.x; Bs[lc+1][lr] = wb.y; Bs[lc+2][lr] = wb.z; Bs[lc+3][lr] = wb.w;
        __syncthreads();
#pragma unroll
        for (int kk = 0; kk < 16; kk++) {
            float a[4], b[4];
#pragma unroll
            for (int i = 0; i < 4; i++) a[i] = As[kk][ty*4 + i];
#pragma unroll
            for (int j = 0; j < 4; j++) b[j] = Bs[kk][tx*4 + j];
#pragma unroll
            for (int i = 0; i < 4; i++)
#pragma unroll
                for (int j = 0; j < 4; j++)
                    acc[i][j] = fmaf(a[i], b[j], acc[i][j]);
        }
        __syncthreads();
    }
#pragma unroll
    for (int i = 0; i < 4; i++) {
        const int m = m0 + ty*4 + i;
#pragma unroll
        for (int j = 0; j < 4; j++) {
            const int n = n0 + tx*4 + j;
            C[(size_t)m * ldc + n] = acc[i][j] + (bias ? bias[n] : 0.0f);
        }
    }
}

// ============================================================================
// RoPE applied in-place to K and V ([MROWS, KVD], one thread per (row,kv,pair))
// ============================================================================
__global__ void rope_kernel(float* __restrict__ K, float* __restrict__ V)
{
    const int total = MROWS * KVD / 2;   // pairs per tensor
    int idx = blockIdx.x * blockDim.x + threadIdx.x;
    if (idx >= 2 * total) return;
    float* ptr = (idx < total) ? K : V;
    int i = (idx < total) ? idx : idx - total;

    const int pair = i & 63;         // d in 0..63
    const int rest = i >> 6;         // row*NKV + kv
    const int kvi  = rest & (NKV - 1);
    const int row  = rest / NKV;
    const int s    = row & (S_LEN - 1);

    const float inv_freq = powf(10000.0f, -(float)(2 * pair) / (float)HD);
    const float ang = (float)s * inv_freq;
    const float c = cosf(ang), sn = sinf(ang);

    const size_t base = (size_t)row * KVD + kvi * HD;
    float x1 = ptr[base + pair];
    float x2 = ptr[base + pair + 64];
    ptr[base + pair]      = x1 * c - x2 * sn;
    ptr[base + pair + 64] = x2 * c + x1 * sn;
}

// ============================================================================
// scores[z] = Q[b,h] * K[b,kv]^T / sqrt(HD), causal block-skip. z = b*H + h
// ============================================================================
__global__ __launch_bounds__(256) void gemm_scores(
    const float* __restrict__ Q, const float* __restrict__ K,
    float* __restrict__ attn)
{
    const int z  = blockIdx.z;
    const int b  = z / NHEADS;
    const int h  = z % NHEADS;
    const int kv = h / NGRP;
    const int m0 = blockIdx.y * 64;
    const int n0 = blockIdx.x * 64;
    if (n0 > m0 + 63) return;   // fully above diagonal: softmax never reads it

    const float* A  = Q + (size_t)b * S_LEN * D_MODEL + h * HD;   // lda = D_MODEL
    const float* Bm = K + (size_t)b * S_LEN * KVD + kv * HD;      // ldb = KVD
    float* C = attn + (size_t)z * S_LEN * S_LEN;                  // ldc = S_LEN
    const float scale = 0.08838834764831845f;  // 1/sqrt(128)

    __shared__ float As[16][64];
    __shared__ float Bs[16][64];
    const int t  = threadIdx.x;
    const int lr = t >> 2;
    const int lc = (t & 3) * 4;
    const int ty = t >> 4;
    const int tx = t & 15;
    float acc[4][4] = {};

    for (int k0 = 0; k0 < HD; k0 += 16) {
        float4 xa = *(const float4*)(A  + (size_t)(m0 + lr) * D_MODEL + k0 + lc);
        float4 wb = *(const float4*)(Bm + (size_t)(n0 + lr) * KVD     + k0 + lc);
        As[lc+0][lr] = xa.x; As[lc+1][lr] = xa.y; As[lc+2][lr] = xa.z; As[lc+3][lr] = xa.w;
        Bs[lc+0][lr] = wb.x; Bs[lc+1][lr] = wb.y; Bs[lc+2][lr] = wb.z; Bs[lc+3][lr] = wb.w;
        __syncthreads();
#pragma unroll
        for (int kk = 0; kk < 16; kk++) {
            float a[4], bb[4];
#pragma unroll
            for (int i = 0; i < 4; i++) a[i] = As[kk][ty*4 + i];
#pragma unroll
            for (int j = 0; j < 4; j++) bb[j] = Bs[kk][tx*4 + j];
#pragma unroll
            for (int i = 0; i < 4; i++)
#pragma unroll
                for (int j = 0; j < 4; j++)
                    acc[i][j] = fmaf(a[i], bb[j], acc[i][j]);
        }
        __syncthreads();
    }
#pragma unroll
    for (int i = 0; i < 4; i++) {
        const int m = m0 + ty*4 + i;
#pragma unroll
        for (int j = 0; j < 4; j++) {
            const int n = n0 + tx*4 + j;
            C[(size_t)m * S_LEN + n] = acc[i][j] * scale;
        }
    }
}

// ============================================================================
// In-place causal softmax over attn rows; zeros beyond the diagonal.
// One block (256 thr) per row; row index r = z*S + q.
// ============================================================================
__global__ __launch_bounds__(256) void softmax_kernel(float* __restrict__ attn)
{
    const int r = blockIdx.x;
    const int q = r & (S_LEN - 1);
    float* row = attn + (size_t)r * S_LEN;
    const int len = q + 1;
    __shared__ float red[256];
    const int t = threadIdx.x;

    float m = -1e30f;
    for (int i = t; i < len; i += 256) m = fmaxf(m, row[i]);
    red[t] = m; __syncthreads();
    for (int s = 128; s > 0; s >>= 1) {
        if (t < s) red[t] = fmaxf(red[t], red[t + s]);
        __syncthreads();
    }
    m = red[0]; __syncthreads();

    float sum = 0.0f;
    for (int i = t; i < len; i += 256) {
        float e = __expf(row[i] - m);
        row[i] = e;
        sum += e;
    }
    red[t] = sum; __syncthreads();
    for (int s = 128; s > 0; s >>= 1) {
        if (t < s) red[t] += red[t + s];
        __syncthreads();
    }
    const float inv = 1.0f / red[0];
    for (int i = t; i < len; i += 256) row[i] *= inv;
    for (int i = len + t; i < S_LEN; i += 256) row[i] = 0.0f;
}

// ============================================================================
// ctx[b,h] = attn[z] * V[b,kv]   (A:[S,S] row-major, B:[S,HD] strided)
// causal: k loop clipped at m0+64 (attn is zero beyond).
// ============================================================================
__global__ __launch_bounds__(256) void gemm_av(
    const float* __restrict__ attn, const float* __restrict__ V,
    float* __restrict__ ctx)
{
    const int z  = blockIdx.z;
    const int b  = z / NHEADS;
    const int h  = z % NHEADS;
    const int kv = h / NGRP;
    const float* A  = attn + (size_t)z * S_LEN * S_LEN;            // lda = S
    const float* Bm = V + (size_t)b * S_LEN * KVD + kv * HD;       // ldb = KVD
    float* C = ctx + (size_t)b * S_LEN * D_MODEL + h * HD;         // ldc = D

    const int m0 = blockIdx.y * 64;
    const int n0 = blockIdx.x * 64;
    const int kmax = m0 + 64;

    __shared__ float As[16][64];
    __shared__ float Bs[16][64];
    const int t  = threadIdx.x;
    const int lr = t >> 2;
    const int lc = (t & 3) * 4;
    const int br = t >> 4;          // 0..15
    const int bc = (t & 15) * 4;    // 0..60
    const int ty = t >> 4;
    const int tx = t & 15;
    float acc[4][4] = {};

    for (int k0 = 0; k0 < kmax; k0 += 16) {
        float4 xa = *(const float4*)(A  + (size_t)(m0 + lr) * S_LEN + k0 + lc);
        float4 vb = *(const float4*)(Bm + (size_t)(k0 + br) * KVD + n0 + bc);
        As[lc+0][lr] = xa.x; As[lc+1][lr] = xa.y; As[lc+2][lr] = xa.z; As[lc+3][lr] = xa.w;
        Bs[br][bc+0] = vb.x; Bs[br][bc+1] = vb.y; Bs[br][bc+2] = vb.z; Bs[br][bc+3] = vb.w;
        __syncthreads();
#pragma unroll
        for (int kk = 0; kk < 16; kk++) {
            float a[4], bb[4];
#pragma unroll
            for (int i = 0; i < 4; i++) a[i] = As[kk][ty*4 + i];
#pragma unroll
            for (int j = 0; j < 4; j++) bb[j] = Bs[kk][tx*4 + j];
#pragma unroll
            for (int i = 0; i < 4; i++)
#pragma unroll
                for (int j = 0; j < 4; j++)
                    acc[i][j] = fmaf(a[i], bb[j], acc[i][j]);
        }
        __syncthreads();
    }
#pragma unroll
    for (int i = 0; i < 4; i++) {
        const int m = m0 + ty*4 + i;
#pragma unroll
        for (int j = 0; j < 4; j++) {
            const int n = n0 + tx*4 + j;
            C[(size_t)m * D_MODEL + n] = acc[i][j];
        }
    }
}

// ============================================================================
// Launch
// ============================================================================
extern "C" void kernel_launch(void* const* d_in, const int* in_sizes, int n_in,
                              void* d_out, int out_size)
{
    const float* query = (const float*)d_in[0];
    // d_in[1] = attention_mask (causal; encoded in kernels, unused)
    const float* Wq = (const float*)d_in[2];
    const float* bq = (const float*)d_in[3];
    const float* Wk = (const float*)d_in[4];
    const float* bk = (const float*)d_in[5];
    const float* Wv = (const float*)d_in[6];
    const float* bv = (const float*)d_in[7];
    const float* Wo = (const float*)d_in[8];
    const float* bo = (const float*)d_in[9];
    float* out = (float*)d_out;

    float *pQ, *pK, *pV, *pCtx, *pAttn;
    cudaGetSymbolAddress((void**)&pQ,   g_Q);
    cudaGetSymbolAddress((void**)&pK,   g_K);
    cudaGetSymbolAddress((void**)&pV,   g_V);
    cudaGetSymbolAddress((void**)&pCtx, g_ctx);
    cudaGetSymbolAddress((void**)&pAttn, g_attn);

    const long long OUT_ELEMS  = (long long)MROWS * D_MODEL;                  // 8,388,608
    const long long ATTN_ELEMS = (long long)BATCH * NHEADS * S_LEN * S_LEN;   // 134,217,728
    float* attn = pAttn;
    if ((long long)out_size >= OUT_ELEMS + ATTN_ELEMS)
        attn = out + OUT_ELEMS;   // reference returns (out, attn): write attn in place

    // 1-3: Q/K/V projections (X * W^T + b)
    gemm_xwt<<<dim3(D_MODEL/64, MROWS/64), 256>>>(query, Wq, bq, pQ,
        MROWS, D_MODEL, D_MODEL, D_MODEL, D_MODEL, D_MODEL);
    gemm_xwt<<<dim3(KVD/64, MROWS/64), 256>>>(query, Wk, bk, pK,
        MROWS, KVD, D_MODEL, D_MODEL, D_MODEL, KVD);
    gemm_xwt<<<dim3(KVD/64, MROWS/64), 256>>>(query, Wv, bv, pV,
        MROWS, KVD, D_MODEL, D_MODEL, D_MODEL, KVD);

    // 4: RoPE on K and V
    {
        int total_threads = 2 * MROWS * KVD / 2;
        rope_kernel<<<(total_threads + 255) / 256, 256>>>(pK, pV);
    }

    // 5: scores = Q K^T / sqrt(hd)  (causal block skip)
    gemm_scores<<<dim3(S_LEN/64, S_LEN/64, BATCH*NHEADS), 256>>>(pQ, pK, attn);

    // 6: causal softmax (in place, writes zeros above diagonal)
    softmax_kernel<<<BATCH*NHEADS*S_LEN, 256>>>(attn);

    // 7: ctx = attn @ V  (k clipped to diagonal)
    gemm_av<<<dim3(HD/64, S_LEN/64, BATCH*NHEADS), 256>>>(attn, pV, pCtx);

    // 8: out = ctx @ Wo^T + bo  -> directly into d_out
    gemm_xwt<<<dim3(D_MODEL/64, MROWS/64), 256>>>(pCtx, Wo, bo, out,
        MROWS, D_MODEL, D_MODEL, D_MODEL, D_MODEL, D_MODEL);
}

// round 2
// speedup vs baseline: 2.6135x; 2.6135x over previous
#include <cuda_runtime.h>
#include <math.h>
#include <stdint.h>

#define D_MODEL 2048
#define S_LEN   2048
#define BATCH   2
#define NHEADS  16
#define NKV     4
#define NGRP    4
#define HD      128
#define KVD     (NKV*HD)        /* 512  */
#define MROWS   (BATCH*S_LEN)   /* 4096 */

// -------- scratch (device globals; no allocation allowed) --------
__device__ float g_Q  [(size_t)MROWS * D_MODEL];
__device__ float g_K  [(size_t)MROWS * KVD];
__device__ float g_V  [(size_t)MROWS * KVD];
__device__ float g_ctx[(size_t)MROWS * D_MODEL];
__device__ float g_attn[(size_t)BATCH * NHEADS * S_LEN * S_LEN];

// ---------------- tf32 helpers ----------------
__device__ __forceinline__ float to_tf32(float x) {
    uint32_t u;
    asm("cvt.rna.tf32.f32 %0, %1;" : "=r"(u) : "f"(x));
    return __uint_as_float(u);
}

__device__ __forceinline__ void mma_tf32(float* d, const uint32_t* a, const uint32_t* b) {
    asm volatile(
        "mma.sync.aligned.m16n8k8.row.col.f32.tf32.tf32.f32 "
        "{%0,%1,%2,%3}, {%4,%5,%6,%7}, {%8,%9}, {%0,%1,%2,%3};\n"
        : "+f"(d[0]), "+f"(d[1]), "+f"(d[2]), "+f"(d[3])
        : "r"(a[0]), "r"(a[1]), "r"(a[2]), "r"(a[3]),
          "r"(b[0]), "r"(b[1]));
}

// Shared-tile strides (padded for conflict-free fragment loads)
#define AK_PAD 20   /* [row][16k] padded to 20 floats: bank=(20m+k)%32 distinct */
#define BN_PAD 136  /* [k][128n] padded to 136: bank=(8k+n)%32 distinct        */

// ============================================================================
// C = X * W^T + bias  (X:[M,Kd] lda row-major, W:[N,Kd] ldb row-major)
// Block 128x128, BK=16, 8 warps (2m x 4n), warp tile 64x32 (4x4 m16n8k8).
// ============================================================================
__global__ __launch_bounds__(256) void gemm_xwt_tc(
    const float* __restrict__ X, const float* __restrict__ W,
    const float* __restrict__ bias, float* __restrict__ C,
    int Kd, int lda, int ldb, int ldc)
{
    __shared__ float As[128 * AK_PAD];
    __shared__ float Bs[128 * AK_PAD];

    const int m0 = blockIdx.y * 128;
    const int n0 = blockIdx.x * 128;
    const int t    = threadIdx.x;
    const int lane = t & 31;
    const int wid  = t >> 5;
    const int wm   = wid & 1;          // 0..1
    const int wn   = wid >> 1;         // 0..3
    const int gid  = lane >> 2;        // 0..7
    const int tig  = lane & 3;         // 0..3

    float acc[4][4][4];
#pragma unroll
    for (int i = 0; i < 4; i++)
#pragma unroll
        for (int j = 0; j < 4; j++)
#pragma unroll
            for (int r = 0; r < 4; r++) acc[i][j][r] = 0.0f;

    // fill indices: each thread 2 float4 per tile (128 rows x 16 k)
    const int fr0 = t >> 2;            // 0..63
    const int fk0 = (t & 3) * 4;       // 0,4,8,12

    for (int k0 = 0; k0 < Kd; k0 += 16) {
#pragma unroll
        for (int h = 0; h < 2; h++) {
            const int row = fr0 + h * 64;
            float4 xa = *(const float4*)(X + (size_t)(m0 + row) * lda + k0 + fk0);
            float4 wb = *(const float4*)(W + (size_t)(n0 + row) * ldb + k0 + fk0);
            xa.x = to_tf32(xa.x); xa.y = to_tf32(xa.y); xa.z = to_tf32(xa.z); xa.w = to_tf32(xa.w);
            wb.x = to_tf32(wb.x); wb.y = to_tf32(wb.y); wb.z = to_tf32(wb.z); wb.w = to_tf32(wb.w);
            *(float4*)(As + row * AK_PAD + fk0) = xa;
            *(float4*)(Bs + row * AK_PAD + fk0) = wb;
        }
        __syncthreads();

#pragma unroll
        for (int ks = 0; ks < 2; ks++) {
            uint32_t af[4][4];
#pragma unroll
            for (int tm = 0; tm < 4; tm++) {
                const float* p = As + (wm * 64 + tm * 16 + gid) * AK_PAD + ks * 8 + tig;
                af[tm][0] = __float_as_uint(p[0]);
                af[tm][1] = __float_as_uint(p[8 * AK_PAD]);
                af[tm][2] = __float_as_uint(p[4]);
                af[tm][3] = __float_as_uint(p[8 * AK_PAD + 4]);
            }
            uint32_t bf[4][2];
#pragma unroll
            for (int tn = 0; tn < 4; tn++) {
                const float* p = Bs + (wn * 32 + tn * 8 + gid) * AK_PAD + ks * 8 + tig;
                bf[tn][0] = __float_as_uint(p[0]);
                bf[tn][1] = __float_as_uint(p[4]);
            }
#pragma unroll
            for (int tm = 0; tm < 4; tm++)
#pragma unroll
                for (int tn = 0; tn < 4; tn++)
                    mma_tf32(acc[tm][tn], af[tm], bf[tn]);
        }
        __syncthreads();
    }

#pragma unroll
    for (int tm = 0; tm < 4; tm++) {
        const int r = m0 + wm * 64 + tm * 16 + gid;
#pragma unroll
        for (int tn = 0; tn < 4; tn++) {
            const int c = n0 + wn * 32 + tn * 8 + tig * 2;
            const float b0 = bias ? bias[c] : 0.0f;
            const float b1 = bias ? bias[c + 1] : 0.0f;
            float2 v0 = make_float2(acc[tm][tn][0] + b0, acc[tm][tn][1] + b1);
            float2 v1 = make_float2(acc[tm][tn][2] + b0, acc[tm][tn][3] + b1);
            *(float2*)(C + (size_t)r * ldc + c) = v0;
            *(float2*)(C + (size_t)(r + 8) * ldc + c) = v1;
        }
    }
}

// ============================================================================
// scores[z] = Q[b,h] * K[b,kv]^T * scale   (causal block skip)
// ============================================================================
__global__ __launch_bounds__(256) void gemm_scores_tc(
    const float* __restrict__ Q, const float* __restrict__ K,
    float* __restrict__ attn)
{
    const int n0 = blockIdx.x * 128;
    const int m0 = blockIdx.y * 128;
    if (n0 > m0) return;   // fully above diagonal

    const int z  = blockIdx.z;
    const int b  = z / NHEADS;
    const int h  = z % NHEADS;
    const int kv = h / NGRP;
    const float* A  = Q + (size_t)b * S_LEN * D_MODEL + h * HD;
    const float* Bm = K + (size_t)b * S_LEN * KVD + kv * HD;
    float* C = attn + (size_t)z * S_LEN * S_LEN;
    const float scale = 0.08838834764831845f;

    __shared__ float As[128 * AK_PAD];
    __shared__ float Bs[128 * AK_PAD];

    const int t    = threadIdx.x;
    const int lane = t & 31;
    const int wid  = t >> 5;
    const int wm   = wid & 1;
    const int wn   = wid >> 1;
    const int gid  = lane >> 2;
    const int tig  = lane & 3;

    float acc[4][4][4];
#pragma unroll
    for (int i = 0; i < 4; i++)
#pragma unroll
        for (int j = 0; j < 4; j++)
#pragma unroll
            for (int r = 0; r < 4; r++) acc[i][j][r] = 0.0f;

    const int fr0 = t >> 2;
    const int fk0 = (t & 3) * 4;

    for (int k0 = 0; k0 < HD; k0 += 16) {
#pragma unroll
        for (int h2 = 0; h2 < 2; h2++) {
            const int row = fr0 + h2 * 64;
            float4 xa = *(const float4*)(A  + (size_t)(m0 + row) * D_MODEL + k0 + fk0);
            float4 wb = *(const float4*)(Bm + (size_t)(n0 + row) * KVD     + k0 + fk0);
            xa.x = to_tf32(xa.x); xa.y = to_tf32(xa.y); xa.z = to_tf32(xa.z); xa.w = to_tf32(xa.w);
            wb.x = to_tf32(wb.x); wb.y = to_tf32(wb.y); wb.z = to_tf32(wb.z); wb.w = to_tf32(wb.w);
            *(float4*)(As + row * AK_PAD + fk0) = xa;
            *(float4*)(Bs + row * AK_PAD + fk0) = wb;
        }
        __syncthreads();

#pragma unroll
        for (int ks = 0; ks < 2; ks++) {
            uint32_t af[4][4];
#pragma unroll
            for (int tm = 0; tm < 4; tm++) {
                const float* p = As + (wm * 64 + tm * 16 + gid) * AK_PAD + ks * 8 + tig;
                af[tm][0] = __float_as_uint(p[0]);
                af[tm][1] = __float_as_uint(p[8 * AK_PAD]);
                af[tm][2] = __float_as_uint(p[4]);
                af[tm][3] = __float_as_uint(p[8 * AK_PAD + 4]);
            }
            uint32_t bf[4][2];
#pragma unroll
            for (int tn = 0; tn < 4; tn++) {
                const float* p = Bs + (wn * 32 + tn * 8 + gid) * AK_PAD + ks * 8 + tig;
                bf[tn][0] = __float_as_uint(p[0]);
                bf[tn][1] = __float_as_uint(p[4]);
            }
#pragma unroll
            for (int tm = 0; tm < 4; tm++)
#pragma unroll
                for (int tn = 0; tn < 4; tn++)
                    mma_tf32(acc[tm][tn], af[tm], bf[tn]);
        }
        __syncthreads();
    }

#pragma unroll
    for (int tm = 0; tm < 4; tm++) {
        const int r = m0 + wm * 64 + tm * 16 + gid;
#pragma unroll
        for (int tn = 0; tn < 4; tn++) {
            const int c = n0 + wn * 32 + tn * 8 + tig * 2;
            float2 v0 = make_float2(acc[tm][tn][0] * scale, acc[tm][tn][1] * scale);
            float2 v1 = make_float2(acc[tm][tn][2] * scale, acc[tm][tn][3] * scale);
            *(float2*)(C + (size_t)r * S_LEN + c) = v0;
            *(float2*)(C + (size_t)(r + 8) * S_LEN + c) = v1;
        }
    }
}

// ============================================================================
// ctx[b,h] = attn[z] * V[b,kv]   (k clipped at diagonal; attn zero above)
// Bs layout [k][n] (V is k-major in gmem along rows)
// ============================================================================
__global__ __launch_bounds__(256) void gemm_av_tc(
    const float* __restrict__ attn, const float* __restrict__ V,
    float* __restrict__ ctx)
{
    const int z  = blockIdx.z;
    const int b  = z / NHEADS;
    const int h  = z % NHEADS;
    const int kv = h / NGRP;
    const float* A  = attn + (size_t)z * S_LEN * S_LEN;
    const float* Bm = V + (size_t)b * S_LEN * KVD + kv * HD;
    float* C = ctx + (size_t)b * S_LEN * D_MODEL + h * HD;

    const int m0 = blockIdx.y * 128;
    const int n0 = 0;                  // HD == 128 == BN
    const int kmax = m0 + 128;

    __shared__ float As[128 * AK_PAD];
    __shared__ float Bs[16 * BN_PAD];

    const int t    = threadIdx.x;
    const int lane = t & 31;
    const int wid  = t >> 5;
    const int wm   = wid & 1;
    const int wn   = wid >> 1;
    const int gid  = lane >> 2;
    const int tig  = lane & 3;

    float acc[4][4][4];
#pragma unroll
    for (int i = 0; i < 4; i++)
#pragma unroll
        for (int j = 0; j < 4; j++)
#pragma unroll
            for (int r = 0; r < 4; r++) acc[i][j][r] = 0.0f;

    const int fr0 = t >> 2;            // A fill: 0..63 (+64)
    const int fk0 = (t & 3) * 4;
    const int vk  = t >> 5;            // B fill: k row 0..7 (+8)
    const int vn4 = (t & 31) * 4;      // n offset 0..124

    for (int k0 = 0; k0 < kmax; k0 += 16) {
#pragma unroll
        for (int h2 = 0; h2 < 2; h2++) {
            const int row = fr0 + h2 * 64;
            float4 xa = *(const float4*)(A + (size_t)(m0 + row) * S_LEN + k0 + fk0);
            xa.x = to_tf32(xa.x); xa.y = to_tf32(xa.y); xa.z = to_tf32(xa.z); xa.w = to_tf32(xa.w);
            *(float4*)(As + row * AK_PAD + fk0) = xa;

            const int kk = vk + h2 * 8;
            float4 vb = *(const float4*)(Bm + (size_t)(k0 + kk) * KVD + n0 + vn4);
            vb.x = to_tf32(vb.x); vb.y = to_tf32(vb.y); vb.z = to_tf32(vb.z); vb.w = to_tf32(vb.w);
            *(float4*)(Bs + kk * BN_PAD + vn4) = vb;
        }
        __syncthreads();

#pragma unroll
        for (int ks = 0; ks < 2; ks++) {
            uint32_t af[4][4];
#pragma unroll
            for (int tm = 0; tm < 4; tm++) {
                const float* p = As + (wm * 64 + tm * 16 + gid) * AK_PAD + ks * 8 + tig;
                af[tm][0] = __float_as_uint(p[0]);
                af[tm][1] = __float_as_uint(p[8 * AK_PAD]);
                af[tm][2] = __float_as_uint(p[4]);
                af[tm][3] = __float_as_uint(p[8 * AK_PAD + 4]);
            }
            uint32_t bf[4][2];
#pragma unroll
            for (int tn = 0; tn < 4; tn++) {
                const float* p = Bs + (ks * 8 + tig) * BN_PAD + wn * 32 + tn * 8 + gid;
                bf[tn][0] = __float_as_uint(p[0]);
                bf[tn][1] = __float_as_uint(p[4 * BN_PAD]);
            }
#pragma unroll
            for (int tm = 0; tm < 4; tm++)
#pragma unroll
                for (int tn = 0; tn < 4; tn++)
                    mma_tf32(acc[tm][tn], af[tm], bf[tn]);
        }
        __syncthreads();
    }

#pragma unroll
    for (int tm = 0; tm < 4; tm++) {
        const int r = m0 + wm * 64 + tm * 16 + gid;
#pragma unroll
        for (int tn = 0; tn < 4; tn++) {
            const int c = n0 + wn * 32 + tn * 8 + tig * 2;
            float2 v0 = make_float2(acc[tm][tn][0], acc[tm][tn][1]);
            float2 v1 = make_float2(acc[tm][tn][2], acc[tm][tn][3]);
            *(float2*)(C + (size_t)r * D_MODEL + c) = v0;
            *(float2*)(C + (size_t)(r + 8) * D_MODEL + c) = v1;
        }
    }
}

// ============================================================================
// RoPE applied in-place to K and V
// ============================================================================
__global__ void rope_kernel(float* __restrict__ K, float* __restrict__ V)
{
    const int total = MROWS * KVD / 2;
    int idx = blockIdx.x * blockDim.x + threadIdx.x;
    if (idx >= 2 * total) return;
    float* ptr = (idx < total) ? K : V;
    int i = (idx < total) ? idx : idx - total;

    const int pair = i & 63;
    const int rest = i >> 6;
    const int kvi  = rest & (NKV - 1);
    const int row  = rest / NKV;
    const int s    = row & (S_LEN - 1);

    const float inv_freq = powf(10000.0f, -(float)(2 * pair) / (float)HD);
    const float ang = (float)s * inv_freq;
    const float c = cosf(ang), sn = sinf(ang);

    const size_t base = (size_t)row * KVD + kvi * HD;
    float x1 = ptr[base + pair];
    float x2 = ptr[base + pair + 64];
    ptr[base + pair]      = x1 * c - x2 * sn;
    ptr[base + pair + 64] = x2 * c + x1 * sn;
}

// ============================================================================
// In-place causal softmax; zeros beyond the diagonal.
// ============================================================================
__global__ __launch_bounds__(256) void softmax_kernel(float* __restrict__ attn)
{
    const int r = blockIdx.x;
    const int q = r & (S_LEN - 1);
    float* row = attn + (size_t)r * S_LEN;
    const int len = q + 1;
    __shared__ float red[256];
    const int t = threadIdx.x;

    float m = -1e30f;
    for (int i = t; i < len; i += 256) m = fmaxf(m, row[i]);
    red[t] = m; __syncthreads();
    for (int s = 128; s > 0; s >>= 1) {
        if (t < s) red[t] = fmaxf(red[t], red[t + s]);
        __syncthreads();
    }
    m = red[0]; __syncthreads();

    float sum = 0.0f;
    for (int i = t; i < len; i += 256) {
        float e = __expf(row[i] - m);
        row[i] = e;
        sum += e;
    }
    red[t] = sum; __syncthreads();
    for (int s = 128; s > 0; s >>= 1) {
        if (t < s) red[t] += red[t + s];
        __syncthreads();
    }
    const float inv = 1.0f / red[0];
    for (int i = t; i < len; i += 256) row[i] *= inv;
    for (int i = len + t; i < S_LEN; i += 256) row[i] = 0.0f;
}

// ============================================================================
// Launch
// ============================================================================
extern "C" void kernel_launch(void* const* d_in, const int* in_sizes, int n_in,
                              void* d_out, int out_size)
{
    const float* query = (const float*)d_in[0];
    const float* Wq = (const float*)d_in[2];
    const float* bq = (const float*)d_in[3];
    const float* Wk = (const float*)d_in[4];
    const float* bk = (const float*)d_in[5];
    const float* Wv = (const float*)d_in[6];
    const float* bv = (const float*)d_in[7];
    const float* Wo = (const float*)d_in[8];
    const float* bo = (const float*)d_in[9];
    float* out = (float*)d_out;

    float *pQ, *pK, *pV, *pCtx, *pAttn;
    cudaGetSymbolAddress((void**)&pQ,   g_Q);
    cudaGetSymbolAddress((void**)&pK,   g_K);
    cudaGetSymbolAddress((void**)&pV,   g_V);
    cudaGetSymbolAddress((void**)&pCtx, g_ctx);
    cudaGetSymbolAddress((void**)&pAttn, g_attn);

    const long long OUT_ELEMS  = (long long)MROWS * D_MODEL;
    const long long ATTN_ELEMS = (long long)BATCH * NHEADS * S_LEN * S_LEN;
    float* attn = pAttn;
    if ((long long)out_size >= OUT_ELEMS + ATTN_ELEMS)
        attn = out + OUT_ELEMS;

    // 1-3: Q/K/V projections
    gemm_xwt_tc<<<dim3(D_MODEL/128, MROWS/128), 256>>>(query, Wq, bq, pQ,
        D_MODEL, D_MODEL, D_MODEL, D_MODEL);
    gemm_xwt_tc<<<dim3(KVD/128, MROWS/128), 256>>>(query, Wk, bk, pK,
        D_MODEL, D_MODEL, D_MODEL, KVD);
    gemm_xwt_tc<<<dim3(KVD/128, MROWS/128), 256>>>(query, Wv, bv, pV,
        D_MODEL, D_MODEL, D_MODEL, KVD);

    // 4: RoPE on K and V
    {
        int total_threads = 2 * MROWS * KVD / 2;
        rope_kernel<<<(total_threads + 255) / 256, 256>>>(pK, pV);
    }

    // 5: scores = Q K^T / sqrt(hd)
    gemm_scores_tc<<<dim3(S_LEN/128, S_LEN/128, BATCH*NHEADS), 256>>>(pQ, pK, attn);

    // 6: causal softmax
    softmax_kernel<<<BATCH*NHEADS*S_LEN, 256>>>(attn);

    // 7: ctx = attn @ V
    gemm_av_tc<<<dim3(1, S_LEN/128, BATCH*NHEADS), 256>>>(attn, pV, pCtx);

    // 8: out = ctx @ Wo^T + bo
    gemm_xwt_tc<<<dim3(D_MODEL/128, MROWS/128), 256>>>(pCtx, Wo, bo, out,
        D_MODEL, D_MODEL, D_MODEL, D_MODEL);
}

// round 3
// speedup vs baseline: 2.9382x; 1.1242x over previous
#include <cuda_runtime.h>
#include <math.h>
#include <stdint.h>

#define D_MODEL 2048
#define S_LEN   2048
#define BATCH   2
#define NHEADS  16
#define NKV     4
#define NGRP    4
#define HD      128
#define KVD     (NKV*HD)        /* 512  */
#define MROWS   (BATCH*S_LEN)   /* 4096 */

// -------- scratch (device globals; no allocation allowed) --------
__device__ float g_Q  [(size_t)MROWS * D_MODEL];
__device__ float g_K  [(size_t)MROWS * KVD];
__device__ float g_V  [(size_t)MROWS * KVD];
__device__ float g_ctx[(size_t)MROWS * D_MODEL];
__device__ float g_attn[(size_t)BATCH * NHEADS * S_LEN * S_LEN];

// ---------------- tf32 helpers ----------------
__device__ __forceinline__ float to_tf32(float x) {
    uint32_t u;
    asm("cvt.rna.tf32.f32 %0, %1;" : "=r"(u) : "f"(x));
    return __uint_as_float(u);
}
__device__ __forceinline__ float4 cvt4(float4 v) {
    v.x = to_tf32(v.x); v.y = to_tf32(v.y); v.z = to_tf32(v.z); v.w = to_tf32(v.w);
    return v;
}
__device__ __forceinline__ void mma_tf32(float* d, const uint32_t* a, const uint32_t* b) {
    asm volatile(
        "mma.sync.aligned.m16n8k8.row.col.f32.tf32.tf32.f32 "
        "{%0,%1,%2,%3}, {%4,%5,%6,%7}, {%8,%9}, {%0,%1,%2,%3};\n"
        : "+f"(d[0]), "+f"(d[1]), "+f"(d[2]), "+f"(d[3])
        : "r"(a[0]), "r"(a[1]), "r"(a[2]), "r"(a[3]),
          "r"(b[0]), "r"(b[1]));
}

#define AK_PAD 20   /* [row][16k] padded: conflict-free fragment LDS */
#define BN_PAD 136  /* [k][128n] padded */

// warp-tile compute: A [128][AK_PAD], B [128][AK_PAD] (both K-major)
__device__ __forceinline__ void compute_kk(
    const float* __restrict__ As, const float* __restrict__ Bs,
    float acc[4][4][4], int wm, int wn, int gid, int tig)
{
#pragma unroll
    for (int ks = 0; ks < 2; ks++) {
        uint32_t af[4][4];
#pragma unroll
        for (int tm = 0; tm < 4; tm++) {
            const float* p = As + (wm*64 + tm*16 + gid)*AK_PAD + ks*8 + tig;
            af[tm][0] = __float_as_uint(p[0]);
            af[tm][1] = __float_as_uint(p[8*AK_PAD]);
            af[tm][2] = __float_as_uint(p[4]);
            af[tm][3] = __float_as_uint(p[8*AK_PAD+4]);
        }
        uint32_t bf[4][2];
#pragma unroll
        for (int tn = 0; tn < 4; tn++) {
            const float* p = Bs + (wn*32 + tn*8 + gid)*AK_PAD + ks*8 + tig;
            bf[tn][0] = __float_as_uint(p[0]);
            bf[tn][1] = __float_as_uint(p[4]);
        }
#pragma unroll
        for (int tm = 0; tm < 4; tm++)
#pragma unroll
            for (int tn = 0; tn < 4; tn++)
                mma_tf32(acc[tm][tn], af[tm], bf[tn]);
    }
}

// warp-tile compute: A [128][AK_PAD] K-major, B [16][BN_PAD] N-major
__device__ __forceinline__ void compute_kn(
    const float* __restrict__ As, const float* __restrict__ Bs,
    float acc[4][4][4], int wm, int wn, int gid, int tig)
{
#pragma unroll
    for (int ks = 0; ks < 2; ks++) {
        uint32_t af[4][4];
#pragma unroll
        for (int tm = 0; tm < 4; tm++) {
            const float* p = As + (wm*64 + tm*16 + gid)*AK_PAD + ks*8 + tig;
            af[tm][0] = __float_as_uint(p[0]);
            af[tm][1] = __float_as_uint(p[8*AK_PAD]);
            af[tm][2] = __float_as_uint(p[4]);
            af[tm][3] = __float_as_uint(p[8*AK_PAD+4]);
        }
        uint32_t bf[4][2];
#pragma unroll
        for (int tn = 0; tn < 4; tn++) {
            const float* p = Bs + (ks*8 + tig)*BN_PAD + wn*32 + tn*8 + gid;
            bf[tn][0] = __float_as_uint(p[0]);
            bf[tn][1] = __float_as_uint(p[4*BN_PAD]);
        }
#pragma unroll
        for (int tm = 0; tm < 4; tm++)
#pragma unroll
            for (int tn = 0; tn < 4; tn++)
                mma_tf32(acc[tm][tn], af[tm], bf[tn]);
    }
}

// ============================================================================
// C = (X * W^T + bias) * scale.  Double-buffered, register-prefetched.
// ============================================================================
__device__ __forceinline__ void gemm_xwt_body(
    const float* __restrict__ X, const float* __restrict__ W,
    const float* __restrict__ bias, float* __restrict__ C,
    int Kd, int lda, int ldb, int ldc, float scale, int m0, int n0)
{
    __shared__ float Ash[2][128*AK_PAD];
    __shared__ float Bsh[2][128*AK_PAD];

    const int t    = threadIdx.x;
    const int lane = t & 31;
    const int wid  = t >> 5;
    const int wm   = wid & 1;
    const int wn   = wid >> 1;
    const int gid  = lane >> 2;
    const int tig  = lane & 3;

    float acc[4][4][4];
#pragma unroll
    for (int i = 0; i < 4; i++)
#pragma unroll
        for (int j = 0; j < 4; j++)
#pragma unroll
            for (int r = 0; r < 4; r++) acc[i][j][r] = 0.0f;

    const int fr0 = t >> 2;
    const int fk0 = (t & 3) * 4;
    const int nt  = Kd >> 4;

    const float* xp0 = X + (size_t)(m0 + fr0)      * lda + fk0;
    const float* xp1 = X + (size_t)(m0 + fr0 + 64) * lda + fk0;
    const float* wp0 = W + (size_t)(n0 + fr0)      * ldb + fk0;
    const float* wp1 = W + (size_t)(n0 + fr0 + 64) * ldb + fk0;

    float4 rA0 = *(const float4*)xp0;
    float4 rA1 = *(const float4*)xp1;
    float4 rB0 = *(const float4*)wp0;
    float4 rB1 = *(const float4*)wp1;
    {
        float* As = Ash[0]; float* Bs = Bsh[0];
        *(float4*)(As + fr0*AK_PAD + fk0)      = cvt4(rA0);
        *(float4*)(As + (fr0+64)*AK_PAD + fk0) = cvt4(rA1);
        *(float4*)(Bs + fr0*AK_PAD + fk0)      = cvt4(rB0);
        *(float4*)(Bs + (fr0+64)*AK_PAD + fk0) = cvt4(rB1);
    }

    for (int i = 0; i < nt; i++) {
        __syncthreads();
        if (i + 1 < nt) {
            const int k0 = (i + 1) << 4;
            rA0 = *(const float4*)(xp0 + k0);
            rA1 = *(const float4*)(xp1 + k0);
            rB0 = *(const float4*)(wp0 + k0);
            rB1 = *(const float4*)(wp1 + k0);
        }
        compute_kk(Ash[i & 1], Bsh[i & 1], acc, wm, wn, gid, tig);
        if (i + 1 < nt) {
            float* As = Ash[(i+1) & 1]; float* Bs = Bsh[(i+1) & 1];
            *(float4*)(As + fr0*AK_PAD + fk0)      = cvt4(rA0);
            *(float4*)(As + (fr0+64)*AK_PAD + fk0) = cvt4(rA1);
            *(float4*)(Bs + fr0*AK_PAD + fk0)      = cvt4(rB0);
            *(float4*)(Bs + (fr0+64)*AK_PAD + fk0) = cvt4(rB1);
        }
    }

#pragma unroll
    for (int tm = 0; tm < 4; tm++) {
        const int r = m0 + wm*64 + tm*16 + gid;
#pragma unroll
        for (int tn = 0; tn < 4; tn++) {
            const int c = n0 + wn*32 + tn*8 + tig*2;
            const float b0 = bias ? bias[c]   : 0.0f;
            const float b1 = bias ? bias[c+1] : 0.0f;
            float2 v0 = make_float2((acc[tm][tn][0]+b0)*scale, (acc[tm][tn][1]+b1)*scale);
            float2 v1 = make_float2((acc[tm][tn][2]+b0)*scale, (acc[tm][tn][3]+b1)*scale);
            *(float2*)(C + (size_t)r     * ldc + c) = v0;
            *(float2*)(C + (size_t)(r+8) * ldc + c) = v1;
        }
    }
}

__global__ __launch_bounds__(256) void gemm_xwt_tc(
    const float* __restrict__ X, const float* __restrict__ W,
    const float* __restrict__ bias, float* __restrict__ C,
    int Kd, int lda, int ldb, int ldc, float scale)
{
    gemm_xwt_body(X, W, bias, C, Kd, lda, ldb, ldc, scale,
                  blockIdx.y * 128, blockIdx.x * 128);
}

// K and V projections in one launch (z selects)
__global__ __launch_bounds__(256) void gemm_kv_tc(
    const float* __restrict__ X,
    const float* __restrict__ Wk, const float* __restrict__ bk, float* __restrict__ Ko,
    const float* __restrict__ Wv, const float* __restrict__ bv, float* __restrict__ Vo)
{
    const float* W = blockIdx.z ? Wv : Wk;
    const float* b = blockIdx.z ? bv : bk;
    float*       C = blockIdx.z ? Vo : Ko;
    gemm_xwt_body(X, W, b, C, D_MODEL, D_MODEL, D_MODEL, KVD,
                  1.0f, blockIdx.y * 128, blockIdx.x * 128);
}

// ============================================================================
// scores[z] = Qs[b,h] * K[b,kv]^T   (Q pre-scaled; causal block skip)
// ============================================================================
__global__ __launch_bounds__(256) void gemm_scores_tc(
    const float* __restrict__ Q, const float* __restrict__ K,
    float* __restrict__ attn)
{
    const int n0 = blockIdx.x * 128;
    const int m0 = blockIdx.y * 128;
    if (n0 > m0) return;

    const int z  = blockIdx.z;
    const int b  = z / NHEADS;
    const int h  = z % NHEADS;
    const int kv = h / NGRP;
    const float* A  = Q + (size_t)b * S_LEN * D_MODEL + h * HD;
    const float* Bm = K + (size_t)b * S_LEN * KVD + kv * HD;
    float* C = attn + (size_t)z * S_LEN * S_LEN;

    __shared__ float Ash[2][128*AK_PAD];
    __shared__ float Bsh[2][128*AK_PAD];

    const int t    = threadIdx.x;
    const int lane = t & 31;
    const int wid  = t >> 5;
    const int wm   = wid & 1;
    const int wn   = wid >> 1;
    const int gid  = lane >> 2;
    const int tig  = lane & 3;

    float acc[4][4][4];
#pragma unroll
    for (int i = 0; i < 4; i++)
#pragma unroll
        for (int j = 0; j < 4; j++)
#pragma unroll
            for (int r = 0; r < 4; r++) acc[i][j][r] = 0.0f;

    const int fr0 = t >> 2;
    const int fk0 = (t & 3) * 4;
    const int nt  = HD >> 4;   // 8

    const float* xp0 = A  + (size_t)(m0 + fr0)      * D_MODEL + fk0;
    const float* xp1 = A  + (size_t)(m0 + fr0 + 64) * D_MODEL + fk0;
    const float* wp0 = Bm + (size_t)(n0 + fr0)      * KVD + fk0;
    const float* wp1 = Bm + (size_t)(n0 + fr0 + 64) * KVD + fk0;

    float4 rA0 = *(const float4*)xp0;
    float4 rA1 = *(const float4*)xp1;
    float4 rB0 = *(const float4*)wp0;
    float4 rB1 = *(const float4*)wp1;
    {
        float* As = Ash[0]; float* Bs = Bsh[0];
        *(float4*)(As + fr0*AK_PAD + fk0)      = cvt4(rA0);
        *(float4*)(As + (fr0+64)*AK_PAD + fk0) = cvt4(rA1);
        *(float4*)(Bs + fr0*AK_PAD + fk0)      = cvt4(rB0);
        *(float4*)(Bs + (fr0+64)*AK_PAD + fk0) = cvt4(rB1);
    }

    for (int i = 0; i < nt; i++) {
        __syncthreads();
        if (i + 1 < nt) {
            const int k0 = (i + 1) << 4;
            rA0 = *(const float4*)(xp0 + k0);
            rA1 = *(const float4*)(xp1 + k0);
            rB0 = *(const float4*)(wp0 + k0);
            rB1 = *(const float4*)(wp1 + k0);
        }
        compute_kk(Ash[i & 1], Bsh[i & 1], acc, wm, wn, gid, tig);
        if (i + 1 < nt) {
            float* As = Ash[(i+1) & 1]; float* Bs = Bsh[(i+1) & 1];
            *(float4*)(As + fr0*AK_PAD + fk0)      = cvt4(rA0);
            *(float4*)(As + (fr0+64)*AK_PAD + fk0) = cvt4(rA1);
            *(float4*)(Bs + fr0*AK_PAD + fk0)      = cvt4(rB0);
            *(float4*)(Bs + (fr0+64)*AK_PAD + fk0) = cvt4(rB1);
        }
    }

#pragma unroll
    for (int tm = 0; tm < 4; tm++) {
        const int r = m0 + wm*64 + tm*16 + gid;
#pragma unroll
        for (int tn = 0; tn < 4; tn++) {
            const int c = n0 + wn*32 + tn*8 + tig*2;
            *(float2*)(C + (size_t)r     * S_LEN + c) = make_float2(acc[tm][tn][0], acc[tm][tn][1]);
            *(float2*)(C + (size_t)(r+8) * S_LEN + c) = make_float2(acc[tm][tn][2], acc[tm][tn][3]);
        }
    }
}

// ============================================================================
// ctx[b,h] = attn[z] * V[b,kv]   (k clipped at diagonal)
// ============================================================================
__global__ __launch_bounds__(256) void gemm_av_tc(
    const float* __restrict__ attn, const float* __restrict__ V,
    float* __restrict__ ctx)
{
    const int z  = blockIdx.z;
    const int b  = z / NHEADS;
    const int h  = z % NHEADS;
    const int kv = h / NGRP;
    const float* A  = attn + (size_t)z * S_LEN * S_LEN;
    const float* Bm = V + (size_t)b * S_LEN * KVD + kv * HD;
    float* C = ctx + (size_t)b * S_LEN * D_MODEL + h * HD;

    const int m0 = blockIdx.y * 128;
    const int nt = (m0 >> 4) + 8;   // k clipped at m0+128

    __shared__ float Ash[2][128*AK_PAD];
    __shared__ float Bsh[2][16*BN_PAD];

    const int t    = threadIdx.x;
    const int lane = t & 31;
    const int wid  = t >> 5;
    const int wm   = wid & 1;
    const int wn   = wid >> 1;
    const int gid  = lane >> 2;
    const int tig  = lane & 3;

    float acc[4][4][4];
#pragma unroll
    for (int i = 0; i < 4; i++)
#pragma unroll
        for (int j = 0; j < 4; j++)
#pragma unroll
            for (int r = 0; r < 4; r++) acc[i][j][r] = 0.0f;

    const int fr0 = t >> 2;
    const int fk0 = (t & 3) * 4;
    const int vk  = t >> 5;          // 0..7
    const int vn4 = (t & 31) * 4;

    const float* ap0 = A  + (size_t)(m0 + fr0)      * S_LEN + fk0;
    const float* ap1 = A  + (size_t)(m0 + fr0 + 64) * S_LEN + fk0;
    const float* vp0 = Bm + (size_t)vk       * KVD + vn4;
    const float* vp1 = Bm + (size_t)(vk + 8) * KVD + vn4;

    float4 rA0 = *(const float4*)ap0;
    float4 rA1 = *(const float4*)ap1;
    float4 rB0 = *(const float4*)vp0;
    float4 rB1 = *(const float4*)vp1;
    {
        float* As = Ash[0]; float* Bs = Bsh[0];
        *(float4*)(As + fr0*AK_PAD + fk0)      = cvt4(rA0);
        *(float4*)(As + (fr0+64)*AK_PAD + fk0) = cvt4(rA1);
        *(float4*)(Bs + vk*BN_PAD + vn4)       = cvt4(rB0);
        *(float4*)(Bs + (vk+8)*BN_PAD + vn4)   = cvt4(rB1);
    }

    for (int i = 0; i < nt; i++) {
        __syncthreads();
        if (i + 1 < nt) {
            const int k0 = (i + 1) << 4;
            rA0 = *(const float4*)(ap0 + k0);
            rA1 = *(const float4*)(ap1 + k0);
            rB0 = *(const float4*)(vp0 + (size_t)k0 * KVD);
            rB1 = *(const float4*)(vp1 + (size_t)k0 * KVD);
        }
        compute_kn(Ash[i & 1], Bsh[i & 1], acc, wm, wn, gid, tig);
        if (i + 1 < nt) {
            float* As = Ash[(i+1) & 1]; float* Bs = Bsh[(i+1) & 1];
            *(float4*)(As + fr0*AK_PAD + fk0)      = cvt4(rA0);
            *(float4*)(As + (fr0+64)*AK_PAD + fk0) = cvt4(rA1);
            *(float4*)(Bs + vk*BN_PAD + vn4)       = cvt4(rB0);
            *(float4*)(Bs + (vk+8)*BN_PAD + vn4)   = cvt4(rB1);
        }
    }

#pragma unroll
    for (int tm = 0; tm < 4; tm++) {
        const int r = m0 + wm*64 + tm*16 + gid;
#pragma unroll
        for (int tn = 0; tn < 4; tn++) {
            const int c = wn*32 + tn*8 + tig*2;
            *(float2*)(C + (size_t)r     * D_MODEL + c) = make_float2(acc[tm][tn][0], acc[tm][tn][1]);
            *(float2*)(C + (size_t)(r+8) * D_MODEL + c) = make_float2(acc[tm][tn][2], acc[tm][tn][3]);
        }
    }
}

// ============================================================================
// RoPE applied in-place to K and V
// ============================================================================
__global__ void rope_kernel(float* __restrict__ K, float* __restrict__ V)
{
    const int total = MROWS * KVD / 2;
    int idx = blockIdx.x * blockDim.x + threadIdx.x;
    if (idx >= 2 * total) return;
    float* ptr = (idx < total) ? K : V;
    int i = (idx < total) ? idx : idx - total;

    const int pair = i & 63;
    const int rest = i >> 6;
    const int kvi  = rest & (NKV - 1);
    const int row  = rest / NKV;
    const int s    = row & (S_LEN - 1);

    const float inv_freq = powf(10000.0f, -(float)(2 * pair) / (float)HD);
    const float ang = (float)s * inv_freq;
    const float c = cosf(ang), sn = sinf(ang);

    const size_t base = (size_t)row * KVD + kvi * HD;
    float x1 = ptr[base + pair];
    float x2 = ptr[base + pair + 64];
    ptr[base + pair]      = x1 * c - x2 * sn;
    ptr[base + pair + 64] = x2 * c + x1 * sn;
}

// ============================================================================
// One-pass online causal softmax; zero-fills above the diagonal.
// ============================================================================
__global__ __launch_bounds__(256) void softmax_kernel(float* __restrict__ attn)
{
    const int r = blockIdx.x;
    const int q = r & (S_LEN - 1);
    float* row = attn + (size_t)r * S_LEN;
    const int len = q + 1;
    const int t = threadIdx.x;

    float m = -1e30f, s = 0.0f;
    const int len4 = len >> 2;
    const float4* row4 = (const float4*)row;
    for (int i = t; i < len4; i += 256) {
        float4 v = row4[i];
        float mx = fmaxf(fmaxf(v.x, v.y), fmaxf(v.z, v.w));
        if (mx > m) { s *= __expf(m - mx); m = mx; }
        s += __expf(v.x-m) + __expf(v.y-m) + __expf(v.z-m) + __expf(v.w-m);
    }
    for (int i = (len4 << 2) + t; i < len; i += 256) {
        float x = row[i];
        if (x > m) { s *= __expf(m - x); m = x; }
        s += __expf(x - m);
    }

    __shared__ float sm[256], ss[256];
    sm[t] = m; ss[t] = s; __syncthreads();
    for (int k = 128; k > 0; k >>= 1) {
        if (t < k) {
            float m2 = sm[t+k], s2 = ss[t+k];
            float M = fmaxf(sm[t], m2);
            ss[t] = ss[t] * __expf(sm[t] - M) + s2 * __expf(m2 - M);
            sm[t] = M;
        }
        __syncthreads();
    }
    const float M   = sm[0];
    const float inv = 1.0f / ss[0];

    float4* w4 = (float4*)row;
    const int S4    = S_LEN >> 2;
    const int len4w = (len + 3) >> 2;   // chunks containing any valid element
    for (int i = t; i < S4; i += 256) {
        if (i < len4w) {
            float4 v = w4[i];
            const int base = i << 2;
            v.x = (base + 0 < len) ? __expf(v.x - M) * inv : 0.0f;
            v.y = (base + 1 < len) ? __expf(v.y - M) * inv : 0.0f;
            v.z = (base + 2 < len) ? __expf(v.z - M) * inv : 0.0f;
            v.w = (base + 3 < len) ? __expf(v.w - M) * inv : 0.0f;
            w4[i] = v;
        } else {
            w4[i] = make_float4(0.0f, 0.0f, 0.0f, 0.0f);
        }
    }
}

// ============================================================================
// Launch
// ============================================================================
extern "C" void kernel_launch(void* const* d_in, const int* in_sizes, int n_in,
                              void* d_out, int out_size)
{
    const float* query = (const float*)d_in[0];
    const float* Wq = (const float*)d_in[2];
    const float* bq = (const float*)d_in[3];
    const float* Wk = (const float*)d_in[4];
    const float* bk = (const float*)d_in[5];
    const float* Wv = (const float*)d_in[6];
    const float* bv = (const float*)d_in[7];
    const float* Wo = (const float*)d_in[8];
    const float* bo = (const float*)d_in[9];
    float* out = (float*)d_out;

    float *pQ, *pK, *pV, *pCtx, *pAttn;
    cudaGetSymbolAddress((void**)&pQ,   g_Q);
    cudaGetSymbolAddress((void**)&pK,   g_K);
    cudaGetSymbolAddress((void**)&pV,   g_V);
    cudaGetSymbolAddress((void**)&pCtx, g_ctx);
    cudaGetSymbolAddress((void**)&pAttn, g_attn);

    const long long OUT_ELEMS  = (long long)MROWS * D_MODEL;
    const long long ATTN_ELEMS = (long long)BATCH * NHEADS * S_LEN * S_LEN;
    float* attn = pAttn;
    if ((long long)out_size >= OUT_ELEMS + ATTN_ELEMS)
        attn = out + OUT_ELEMS;

    const float qscale = 0.08838834764831845f;  // 1/sqrt(128)

    // 1: Q projection (scale folded in)
    gemm_xwt_tc<<<dim3(D_MODEL/128, MROWS/128), 256>>>(query, Wq, bq, pQ,
        D_MODEL, D_MODEL, D_MODEL, D_MODEL, qscale);
    // 2: K + V projections (one launch)
    gemm_kv_tc<<<dim3(KVD/128, MROWS/128, 2), 256>>>(query, Wk, bk, pK, Wv, bv, pV);

    // 3: RoPE on K and V
    {
        int total_threads = 2 * MROWS * KVD / 2;
        rope_kernel<<<(total_threads + 255) / 256, 256>>>(pK, pV);
    }

    // 4: scores = Qs K^T (causal block skip)
    gemm_scores_tc<<<dim3(S_LEN/128, S_LEN/128, BATCH*NHEADS), 256>>>(pQ, pK, attn);

    // 5: one-pass causal softmax
    softmax_kernel<<<BATCH*NHEADS*S_LEN, 256>>>(attn);

    // 6: ctx = attn @ V
    gemm_av_tc<<<dim3(1, S_LEN/128, BATCH*NHEADS), 256>>>(attn, pV, pCtx);

    // 7: out = ctx @ Wo^T + bo
    gemm_xwt_tc<<<dim3(D_MODEL/128, MROWS/128), 256>>>(pCtx, Wo, bo, out,
        D_MODEL, D_MODEL, D_MODEL, D_MODEL, 1.0f);
}